// round 1
// baseline (speedup 1.0000x reference)
#include <cuda_runtime.h>

#define NB   16
#define NTAU 10
#define ND   6
#define NN   512
#define NW   9
#define NTN  4
#define NHID 64
#define NOUT 2
#define KC   54            // D*W, K-chunk per t
#define K0   540           // TAU*KC
#define TILE_M 32
#define NTHREADS 256
#define MS   36            // padded m_s token-stride (4-way STS conflict, float4-aligned reads)

__global__ __launch_bounds__(NTHREADS, 2)
void tsdcd_kernel(const float* __restrict__ x,
                  const float* __restrict__ mask_param,
                  const float* __restrict__ u,
                  const float* __restrict__ W0,
                  const float* __restrict__ b0,
                  const float* __restrict__ W1,
                  const float* __restrict__ b1,
                  const float* __restrict__ W2,
                  const float* __restrict__ b2,
                  float* __restrict__ out)
{
    __shared__ float E_s[K0];            //  2160 B : exp(-mask_param) slice for current i
    __shared__ float W0_s[KC*NHID];      // 13824 B
    __shared__ float m_s[KC*MS];         //  7776 B
    __shared__ float h_s[TILE_M*NHID];   //  8192 B
    __shared__ float W1_s[NHID*NHID];    // 16384 B   (total 48336 B <= 48KB static)

    const int tid    = threadIdx.x;
    const int token0 = blockIdx.x * TILE_M;
    const int h  = tid & (NHID-1);
    const int g  = tid >> 6;       // 0..3
    const int tb = g * 8;          // token sub-tile base

    for (int i = 0; i < ND; ++i) {
        // ---- E slice: exp(-mask_param[t, i, :, :]) ----
        for (int idx = tid; idx < K0; idx += NTHREADS) {
            int t = idx / KC;
            int r = idx - t * KC;
            E_s[idx] = __expf(-mask_param[(t*ND + i)*KC + r]);
        }

        float acc[8];
        #pragma unroll
        for (int r = 0; r < 8; ++r) acc[r] = 0.f;

        // ---- layer0: K-chunked over t ----
        for (int t = 0; t < NTAU; ++t) {
            __syncthreads();   // protect W0_s/m_s (and first-iter E_s) from prior readers

            // stage W0 chunk [KC][NHID]
            const float4* W0p = (const float4*)(W0 + ((size_t)i*K0 + (size_t)t*KC)*NHID);
            float4* W0d = (float4*)W0_s;
            for (int idx = tid; idx < (KC*NHID)/4; idx += NTHREADS)
                W0d[idx] = W0p[idx];

            // produce m chunk: m[tok][kk] = x_window * (u / (u + E*(1-u)))
            const int ubase_t = t*ND + i;
            for (int idx = tid; idx < KC*TILE_M; idx += NTHREADS) {
                int tok = idx / KC;            // lanes sweep kk -> coalesced u loads
                int kk  = idx - tok*KC;
                int token = token0 + tok;
                int n = token >> 4;
                int b = token & (NB-1);
                int j = kk / NW;
                int w = kk - j*NW;
                int col = n + w - NTN;
                float xv = 0.f;
                if ((unsigned)col < NN)
                    xv = x[((b*NTAU + t)*ND + j)*NN + col];
                float uv = u[((size_t)token*(ND*NTAU) + ubase_t)*KC + kk];
                float e  = E_s[t*KC + kk];
                float mask = __fdividef(uv, fmaf(e, 1.f - uv, uv));
                m_s[kk*MS + tok] = xv * mask;
            }
            __syncthreads();

            // accumulate: 8-token x 1-h microtile per thread
            #pragma unroll 6
            for (int kk = 0; kk < KC; ++kk) {
                float wv = W0_s[kk*NHID + h];
                const float4 m0 = *(const float4*)(m_s + kk*MS + tb);
                const float4 m1 = *(const float4*)(m_s + kk*MS + tb + 4);
                acc[0] = fmaf(m0.x, wv, acc[0]);
                acc[1] = fmaf(m0.y, wv, acc[1]);
                acc[2] = fmaf(m0.z, wv, acc[2]);
                acc[3] = fmaf(m0.w, wv, acc[3]);
                acc[4] = fmaf(m1.x, wv, acc[4]);
                acc[5] = fmaf(m1.y, wv, acc[5]);
                acc[6] = fmaf(m1.z, wv, acc[6]);
                acc[7] = fmaf(m1.w, wv, acc[7]);
            }
        }

        // ---- layer0 epilogue: bias + relu -> h_s ----
        {
            float bb = b0[i*NHID + h];
            #pragma unroll
            for (int r = 0; r < 8; ++r)
                h_s[(tb + r)*NHID + h] = fmaxf(acc[r] + bb, 0.f);
        }
        // stage W1[i]
        {
            const float4* W1p = (const float4*)(W1 + (size_t)i*NHID*NHID);
            float4* W1d = (float4*)W1_s;
            for (int idx = tid; idx < (NHID*NHID)/4; idx += NTHREADS)
                W1d[idx] = W1p[idx];
        }
        __syncthreads();

        // ---- layer1 ----
        float acc2[8];
        #pragma unroll
        for (int r = 0; r < 8; ++r) acc2[r] = 0.f;
        #pragma unroll 8
        for (int k = 0; k < NHID; ++k) {
            float wv = W1_s[k*NHID + h];
            #pragma unroll
            for (int r = 0; r < 8; ++r)
                acc2[r] = fmaf(h_s[(tb + r)*NHID + k], wv, acc2[r]);
        }
        __syncthreads();   // everyone done reading h_s
        {
            float bb = b1[i*NHID + h];
            #pragma unroll
            for (int r = 0; r < 8; ++r)
                h_s[(tb + r)*NHID + h] = fmaxf(acc2[r] + bb, 0.f);
        }
        __syncthreads();

        // ---- layer2: 64 threads, one (token, o) each ----
        if (tid < TILE_M*NOUT) {
            int tok = tid >> 1;
            int o   = tid & 1;
            float a = b2[i*NOUT + o];
            #pragma unroll 8
            for (int k = 0; k < NHID; ++k)
                a = fmaf(h_s[tok*NHID + k], W2[((size_t)i*NHID + k)*NOUT + o], a);
            int token = token0 + tok;
            int n = token >> 4;
            int b = token & (NB-1);
            out[(((size_t)b*ND + i)*NN + n)*NOUT + o] = a;
        }
        __syncthreads();   // end-of-i barrier before E_s / h_s reuse
    }
}

extern "C" void kernel_launch(void* const* d_in, const int* in_sizes, int n_in,
                              void* d_out, int out_size)
{
    const float* x  = (const float*)d_in[0];
    const float* mp = (const float*)d_in[1];
    const float* u  = (const float*)d_in[2];
    const float* W0 = (const float*)d_in[3];
    const float* b0 = (const float*)d_in[4];
    const float* W1 = (const float*)d_in[5];
    const float* b1 = (const float*)d_in[6];
    const float* W2 = (const float*)d_in[7];
    const float* b2 = (const float*)d_in[8];
    float* out = (float*)d_out;

    dim3 grid((NB * NN) / TILE_M);   // 256 blocks of 32 tokens
    tsdcd_kernel<<<grid, NTHREADS>>>(x, mp, u, W0, b0, W1, b1, W2, b2, out);
}

// round 2
// speedup vs baseline: 1.2926x; 1.2926x over previous
#include <cuda_runtime.h>

#define NB     16
#define NTAU   10
#define ND     6
#define NN     512
#define NW     9
#define NHID   64
#define KC     54           // D*W
#define TPB    64           // threads per block = tokens per block
#define US     55           // u_s row stride (odd -> conflict-free consumer reads)
#define NTILES 128          // 8192 tokens / 64

typedef unsigned long long ull;

__device__ __forceinline__ ull ffma2(ull a, ull b, ull c) {
    ull d;
    asm("fma.rn.f32x2 %0, %1, %2, %3;" : "=l"(d) : "l"(a), "l"(b), "l"(c));
    return d;
}
__device__ __forceinline__ ull pack2(float x) {
    ull d;
    asm("mov.b64 %0, {%1, %1};" : "=l"(d) : "f"(x));
    return d;
}
__device__ __forceinline__ float2 unpack2(ull v) {
    float2 r;
    asm("mov.b64 {%0, %1}, %2;" : "=f"(r.x), "=f"(r.y) : "l"(v));
    return r;
}

__global__ __launch_bounds__(TPB, 8)   // cap regs at 128
void tsdcd_kernel(const float* __restrict__ x,
                  const float* __restrict__ mask_param,
                  const float* __restrict__ u,
                  const float* __restrict__ W0,
                  const float* __restrict__ b0,
                  const float* __restrict__ W1,
                  const float* __restrict__ b1,
                  const float* __restrict__ W2,
                  const float* __restrict__ b2,
                  float* __restrict__ out)
{
    __shared__ float u_s[TPB * US];        // 14080 B
    __shared__ float w_s[NHID * NHID];     // 16384 B : W0 chunk (54x64) / W1 (64x64)
    __shared__ float x_s[6 * 12 * 17];     //  4896 B : [j][colw][b], b-dim padded to 17
    __shared__ float E_s[NTAU * KC];       //  2160 B
    __shared__ float b0_s[NHID], b1_s[NHID], W2_s[NHID * 2], b2_s[2];

    const int tid = threadIdx.x;
    const int blk = blockIdx.x;          // token tile (0..127)
    const int i   = blockIdx.y;          // output channel d-index (0..5)
    const int token = blk * TPB + tid;
    const int b_idx = token & (NB - 1);
    const int n_idx = token >> 4;
    const int n_loc = tid >> 4;          // 0..3
    const int nb0   = blk * 4;           // first n in tile

    // ---- one-time staging: E = exp(-mask_param[:, i, :, :]), biases, W2 ----
    for (int e = tid; e < NTAU * KC; e += TPB) {
        int t = e / KC, r = e - t * KC;
        E_s[e] = __expf(-mask_param[(t * ND + i) * KC + r]);
    }
    b0_s[tid] = b0[i * NHID + tid];
    b1_s[tid] = b1[i * NHID + tid];
    W2_s[tid]       = W2[i * NHID * 2 + tid];
    W2_s[tid + 64]  = W2[i * NHID * 2 + tid + 64];
    if (tid < 2) b2_s[tid] = b2[i * 2 + tid];

    ull acc[32];
    #pragma unroll
    for (int p = 0; p < 32; ++p) acc[p] = 0ULL;

    // =================== layer 0 ===================
    for (int t = 0; t < NTAU; ++t) {
        __syncthreads();   // staging buffers free (also covers one-time staging)

        // stage W0 chunk [54][64]
        {
            const float4* src = (const float4*)(W0 + ((size_t)i * 540 + t * KC) * NHID);
            float4* dst = (float4*)w_s;
            for (int e = tid; e < (KC * NHID) / 4; e += TPB) dst[e] = src[e];
        }
        // stage u chunk: rows of 54 per token, coalesced float2 loads
        {
            const float* ub = u + (size_t)(t * ND + i) * KC;
            for (int e = tid; e < TPB * (KC / 2); e += TPB) {
                int tok = e / 27;
                int kp  = e - tok * 27;
                float2 v = *(const float2*)(ub + (size_t)(blk * TPB + tok) * (60 * KC) + 2 * kp);
                u_s[tok * US + 2 * kp]     = v.x;
                u_s[tok * US + 2 * kp + 1] = v.y;
            }
        }
        // stage x window tile: x_s[(j*12+colw)*17 + b], colw = local col (0..11)
        {
            for (int e = tid; e < 6 * 12 * NB; e += TPB) {
                int colw = e % 12;
                int j    = (e / 12) % 6;
                int bb   = e / 72;
                int col  = nb0 + colw - 4;
                float v = 0.f;
                if ((unsigned)col < NN)
                    v = x[((bb * NTAU + t) * ND + j) * NN + col];
                x_s[(j * 12 + colw) * 17 + bb] = v;
            }
        }
        __syncthreads();

        // consume: m produced in registers, w broadcast from smem
        const float* urow = u_s + tid * US;
        for (int j = 0; j < 6; ++j) {
            const float* xr = x_s + (j * 12 + n_loc) * 17 + b_idx;
            const float* er = E_s + t * KC + j * NW;
            const float* ur = urow + j * NW;
            #pragma unroll
            for (int w = 0; w < NW; ++w) {
                float uv = ur[w];
                float ev = er[w];
                float xv = xr[w * 17];
                float den  = fmaf(ev, 1.0f - uv, uv);
                float m    = xv * __fdividef(uv, den);
                ull mdup   = pack2(m);
                const ulonglong2* wr = (const ulonglong2*)(w_s + (j * NW + w) * NHID);
                #pragma unroll
                for (int q = 0; q < 16; ++q) {
                    ulonglong2 wv = wr[q];
                    acc[2 * q]     = ffma2(mdup, wv.x, acc[2 * q]);
                    acc[2 * q + 1] = ffma2(mdup, wv.y, acc[2 * q + 1]);
                }
            }
        }
    }

    // bias + relu -> h[64] in registers
    float h[NHID];
    #pragma unroll
    for (int p = 0; p < 32; ++p) {
        float2 v = unpack2(acc[p]);
        h[2 * p]     = fmaxf(v.x + b0_s[2 * p], 0.f);
        h[2 * p + 1] = fmaxf(v.y + b0_s[2 * p + 1], 0.f);
    }

    // stage W1 [64][64]
    __syncthreads();
    {
        const float4* src = (const float4*)(W1 + (size_t)i * NHID * NHID);
        float4* dst = (float4*)w_s;
        for (int e = tid; e < (NHID * NHID) / 4; e += TPB) dst[e] = src[e];
    }
    __syncthreads();

    // =================== layer 1 (+ layer 2 fused) ===================
    float o0 = b2_s[0], o1 = b2_s[1];
    for (int half = 0; half < 2; ++half) {
        ull acc2[16];
        #pragma unroll
        for (int p = 0; p < 16; ++p) acc2[p] = 0ULL;
        #pragma unroll
        for (int k = 0; k < NHID; ++k) {
            ull hdup = pack2(h[k]);
            const ulonglong2* wr = (const ulonglong2*)(w_s + k * NHID + half * 32);
            #pragma unroll
            for (int q = 0; q < 8; ++q) {
                ulonglong2 wv = wr[q];
                acc2[2 * q]     = ffma2(hdup, wv.x, acc2[2 * q]);
                acc2[2 * q + 1] = ffma2(hdup, wv.y, acc2[2 * q + 1]);
            }
        }
        #pragma unroll
        for (int p = 0; p < 16; ++p) {
            float2 v = unpack2(acc2[p]);
            int g0 = half * 32 + 2 * p;
            float v0 = fmaxf(v.x + b1_s[g0], 0.f);
            float v1 = fmaxf(v.y + b1_s[g0 + 1], 0.f);
            o0 = fmaf(v0, W2_s[g0 * 2],     o0);
            o1 = fmaf(v0, W2_s[g0 * 2 + 1], o1);
            o0 = fmaf(v1, W2_s[g0 * 2 + 2], o0);
            o1 = fmaf(v1, W2_s[g0 * 2 + 3], o1);
        }
    }

    // out[b][i][n][o]
    ((float2*)out)[(size_t)(b_idx * ND + i) * NN + n_idx] = make_float2(o0, o1);
}

extern "C" void kernel_launch(void* const* d_in, const int* in_sizes, int n_in,
                              void* d_out, int out_size)
{
    const float* x  = (const float*)d_in[0];
    const float* mp = (const float*)d_in[1];
    const float* u  = (const float*)d_in[2];
    const float* W0 = (const float*)d_in[3];
    const float* b0 = (const float*)d_in[4];
    const float* W1 = (const float*)d_in[5];
    const float* b1 = (const float*)d_in[6];
    const float* W2 = (const float*)d_in[7];
    const float* b2 = (const float*)d_in[8];
    float* out = (float*)d_out;

    dim3 grid(NTILES, ND);
    tsdcd_kernel<<<grid, TPB>>>(x, mp, u, W0, b0, W1, b1, W2, b2, out);
}

// round 5
// speedup vs baseline: 1.8561x; 1.4359x over previous
#include <cuda_runtime.h>
#include <cstdint>

#define NB     16
#define NTAU   10
#define ND     6
#define NN     512
#define NW     9
#define NHID   64
#define KC     54
#define TILE_M 128
#define TPB    256
#define NTILE  64
#define DYN_BYTES (98304 + 128)

typedef unsigned long long ull;

// W0 pre-converted: [i*10+t] tiles of 16KB (8KB hi plane + 8KB lo plane), swizzled [n][kk] bf16
__device__ __align__(1024) unsigned char g_w0bf[60 * 16384];

__device__ __forceinline__ uint32_t smem_u32(const void* p) {
    uint32_t a;
    asm("{ .reg .u64 t; cvta.to.shared.u64 t, %1; cvt.u32.u64 %0, t; }" : "=r"(a) : "l"(p));
    return a;
}
__device__ __forceinline__ ull ffma2(ull a, ull b, ull c) {
    ull d; asm("fma.rn.f32x2 %0, %1, %2, %3;" : "=l"(d) : "l"(a), "l"(b), "l"(c)); return d;
}
__device__ __forceinline__ ull pack2(float x) {
    ull d; asm("mov.b64 %0, {%1, %1};" : "=l"(d) : "f"(x)); return d;
}
__device__ __forceinline__ float2 unpack2(ull v) {
    float2 r; asm("mov.b64 {%0, %1}, %2;" : "=f"(r.x), "=f"(r.y) : "l"(v)); return r;
}
__device__ __forceinline__ uint32_t f2bf_bits(float v) {   // RNE bf16
    uint32_t u = __float_as_uint(v);
    return (u + 0x7FFFu + ((u >> 16) & 1u)) >> 16;
}
__device__ __forceinline__ uint32_t cvt_bf16x2(float hi, float lo) {
    uint32_t r; asm("cvt.rn.bf16x2.f32 %0, %1, %2;" : "=r"(r) : "f"(hi), "f"(lo)); return r;
}
__device__ __forceinline__ void ldsm4(uint32_t a, uint32_t& r0, uint32_t& r1, uint32_t& r2, uint32_t& r3) {
    asm volatile("ldmatrix.sync.aligned.m8n8.x4.shared.b16 {%0,%1,%2,%3}, [%4];"
                 : "=r"(r0), "=r"(r1), "=r"(r2), "=r"(r3) : "r"(a));
}
__device__ __forceinline__ void mma_bf16(float* d, uint32_t a0, uint32_t a1, uint32_t a2, uint32_t a3,
                                         uint32_t b0, uint32_t b1) {
    asm volatile("mma.sync.aligned.m16n8k16.row.col.f32.bf16.bf16.f32 "
                 "{%0,%1,%2,%3}, {%4,%5,%6,%7}, {%8,%9}, {%0,%1,%2,%3};"
                 : "+f"(d[0]), "+f"(d[1]), "+f"(d[2]), "+f"(d[3])
                 : "r"(a0), "r"(a1), "r"(a2), "r"(a3), "r"(b0), "r"(b1));
}
#define CP16(dst, src) asm volatile("cp.async.cg.shared.global [%0], [%1], 16;" :: "r"(dst), "l"(src))
#define CP_COMMIT()    asm volatile("cp.async.commit_group;" ::: "memory")
#define CP_WAIT0()     asm volatile("cp.async.wait_group 0;" ::: "memory")

// ------------ prep: W0 -> swizzled bf16 hi/lo tile images ------------
__global__ void prep_w0(const float* __restrict__ W0)
{
    const int blk = blockIdx.x;                 // i*10 + t
    const int i = blk / 10, t = blk % 10;
    const float* src = W0 + ((size_t)i * 540 + t * KC) * NHID;
    unsigned char* hi = g_w0bf + (size_t)blk * 16384;
    unsigned char* lo = hi + 8192;
    for (int e = threadIdx.x; e < 4096; e += 256) {
        int kk = e >> 6, n = e & 63;
        float v = (kk < KC) ? src[kk * 64 + n] : 0.f;
        uint32_t hb = f2bf_bits(v);
        float hf = __uint_as_float(hb << 16);
        uint32_t lb = f2bf_bits(v - hf);
        uint32_t off = (uint32_t)(n * 128 + kk * 2) ^ ((uint32_t)(n & 7) << 4);
        *(uint16_t*)(hi + off) = (uint16_t)hb;
        *(uint16_t*)(lo + off) = (uint16_t)lb;
    }
}

// ------------ main kernel ------------
__global__ __launch_bounds__(TPB, 2)
void tsdcd_kernel(const float* __restrict__ x,
                  const float* __restrict__ mask_param,
                  const float* __restrict__ u,
                  const float* __restrict__ b0,
                  const float* __restrict__ W1,
                  const float* __restrict__ b1,
                  const float* __restrict__ W2,
                  const float* __restrict__ b2,
                  float* __restrict__ out)
{
    extern __shared__ unsigned char dyn_raw[];
    __shared__ float E_s[NTAU * KC];
    __shared__ float x_s[1632];
    __shared__ float b0_s[NHID], b1_s[NHID], W2_s[128], b2_s[2];
    __shared__ unsigned char lut_s[KC];
    __shared__ float2 po_s[TPB];

    const uint32_t raw_u = smem_u32(dyn_raw);
    const uint32_t dynb  = (raw_u + 127u) & ~127u;
    unsigned char* dyn = dyn_raw + (dynb - raw_u);

    const int tid  = threadIdx.x;
    const int w    = tid >> 5;
    const int lane = tid & 31;
    const int i    = blockIdx.y;
    const int tile0 = blockIdx.x * TILE_M;
    const int n0    = tile0 >> 4;

    // ---- stage constants ----
    for (int e = tid; e < NTAU * KC; e += TPB) {
        int t = e / KC, r = e - t * KC;
        E_s[e] = __expf(-mask_param[(t * ND + i) * KC + r]);
    }
    if (tid < KC) lut_s[tid] = (unsigned char)((tid / NW) * 16 + tid % NW);
    if (tid < NHID) { b0_s[tid] = b0[i * NHID + tid]; b1_s[tid] = b1[i * NHID + tid]; }
    if (tid < 128) W2_s[tid] = W2[i * 128 + tid];
    if (tid < 2)   b2_s[tid] = b2[i * 2 + tid];
    {   // zero A region (padding cols 54..63 must stay 0)
        float4 z = make_float4(0.f, 0.f, 0.f, 0.f);
        float4* az = (float4*)dyn;
        #pragma unroll
        for (int e = tid; e < 4096; e += TPB) az[e] = z;
    }

    float d[8][4];
    #pragma unroll
    for (int q = 0; q < 8; ++q)
        #pragma unroll
        for (int c = 0; c < 4; ++c) d[q][c] = 0.f;

    float2 ur[14];
    float  xr[6];

    // per-lane ldmatrix geometry
    const int rowA = (w << 4) + (lane & 15);
    const uint32_t aoff = (uint32_t)rowA * 128;
    const uint32_t axr  = (uint32_t)(rowA & 7) << 4;
    const int nB_ = lane & 15;
    const uint32_t bxr  = (uint32_t)(nB_ & 7) << 4;
    const uint32_t colsel = (uint32_t)(lane >> 4) << 4;

    // ---------- lambdas ----------
    auto issue_loads = [&](int t) {
        #pragma unroll
        for (int it = 0; it < 14; ++it) {
            int p = tid + it * 256;
            if (p < 3456) {
                int r = (p * 4855) >> 17;      // p/27
                int q = p - r * 27;
                ur[it] = *(const float2*)(u + (size_t)(tile0 + r) * 3240 + (t * ND + i) * KC + 2 * q);
            }
        }
        #pragma unroll
        for (int it = 0; it < 6; ++it) {
            int e = tid + it * 256;
            int colw = e & 15;
            int j = (e >> 4) % 6;
            int bb = e / 96;
            int col = n0 + colw - 4;
            float v = 0.f;
            if ((unsigned)col < NN) v = x[((bb * NTAU + t) * ND + j) * NN + col];
            xr[it] = v;
        }
        const unsigned char* bsrc = g_w0bf + (size_t)(i * 10 + t) * 16384;
        uint32_t bdst = dynb + 65536 + (uint32_t)(t & 1) * 16384;
        #pragma unroll
        for (int c = 0; c < 4; ++c)
            CP16(bdst + tid * 16 + c * 4096, bsrc + tid * 16 + c * 4096);
        CP_COMMIT();
    };
    auto store_x = [&]() {
        #pragma unroll
        for (int it = 0; it < 6; ++it) {
            int e = tid + it * 256;
            int colw = e & 15;
            int j = (e >> 4) % 6;
            int bb = e / 96;
            x_s[(j * 16 + colw) * 17 + bb] = xr[it];
        }
    };
    auto do_math = [&](int t, int s) {
        unsigned char* ahp = dyn + s * 32768;
        #pragma unroll
        for (int it = 0; it < 14; ++it) {
            int p = tid + it * 256;
            if (p < 3456) {
                int r = (p * 4855) >> 17;
                int q = p - r * 27;
                int kk = 2 * q;
                float2 uv = ur[it];
                float2 ev = *(const float2*)&E_s[t * KC + kk];
                int nl = r >> 4, bb = r & 15;
                float x0 = x_s[(lut_s[kk] + nl) * 17 + bb];
                float x1 = x_s[(lut_s[kk + 1] + nl) * 17 + bb];
                float m0 = x0 * __fdividef(uv.x, fmaf(ev.x, 1.f - uv.x, uv.x));
                float m1 = x1 * __fdividef(uv.y, fmaf(ev.y, 1.f - uv.y, uv.y));
                uint32_t h2 = cvt_bf16x2(m1, m0);              // lo16 = m0
                float hf0 = __uint_as_float(h2 << 16);
                float hf1 = __uint_as_float(h2 & 0xFFFF0000u);
                uint32_t l2 = cvt_bf16x2(m1 - hf1, m0 - hf0);
                uint32_t off = (uint32_t)(r * 128 + 4 * q) ^ ((uint32_t)(r & 7) << 4);
                *(uint32_t*)(ahp + off)         = h2;
                *(uint32_t*)(ahp + 16384 + off) = l2;
            }
        }
    };
    auto consume = [&](int s) {
        uint32_t Abase = dynb + (uint32_t)s * 32768;
        uint32_t Bbase = dynb + 65536 + (uint32_t)s * 16384;
        #pragma unroll
        for (int k = 0; k < 4; ++k) {
            uint32_t colb = (uint32_t)k * 32 + colsel;
            uint32_t aa = Abase + aoff + (colb ^ axr);
            uint32_t ah0, ah1, ah2, ah3, al0, al1, al2, al3;
            ldsm4(aa,         ah0, ah1, ah2, ah3);
            ldsm4(aa + 16384, al0, al1, al2, al3);
            #pragma unroll
            for (int g = 0; g < 4; ++g) {
                uint32_t ba = Bbase + ((uint32_t)g << 11) + (uint32_t)nB_ * 128 + (colb ^ bxr);
                uint32_t bh0, bh1, bh2, bh3, bl0, bl1, bl2, bl3;
                ldsm4(ba,        bh0, bh1, bh2, bh3);
                ldsm4(ba + 8192, bl0, bl1, bl2, bl3);
                mma_bf16(d[2 * g],     ah0, ah1, ah2, ah3, bh0, bh2);
                mma_bf16(d[2 * g],     al0, al1, al2, al3, bh0, bh2);
                mma_bf16(d[2 * g],     ah0, ah1, ah2, ah3, bl0, bl2);
                mma_bf16(d[2 * g + 1], ah0, ah1, ah2, ah3, bh1, bh3);
                mma_bf16(d[2 * g + 1], al0, al1, al2, al3, bh1, bh3);
                mma_bf16(d[2 * g + 1], ah0, ah1, ah2, ah3, bl1, bl3);
            }
        }
    };

    // ---------- pipeline ----------
    issue_loads(0);
    CP_WAIT0();
    store_x();
    __syncthreads();
    do_math(0, 0);
    __syncthreads();
    for (int t = 1; t < NTAU; ++t) {
        int s = t & 1;
        issue_loads(t);
        consume(s ^ 1);
        CP_WAIT0();
        store_x();
        __syncthreads();
        do_math(t, s);
        __syncthreads();
    }
    consume(1);
    __syncthreads();

    // ---------- epilogue: bias+relu -> h_s (rows stride 68), stage W1 ----------
    {
        float* hs = (float*)dyn;
        int rb = (w << 4) + (lane >> 2);
        int cb = (lane & 3) * 2;
        #pragma unroll
        for (int nt = 0; nt < 8; ++nt) {
            int c = nt * 8 + cb;
            float ba = b0_s[c], bbv = b0_s[c + 1];
            *(float2*)&hs[rb * 68 + c]       = make_float2(fmaxf(d[nt][0] + ba, 0.f), fmaxf(d[nt][1] + bbv, 0.f));
            *(float2*)&hs[(rb + 8) * 68 + c] = make_float2(fmaxf(d[nt][2] + ba, 0.f), fmaxf(d[nt][3] + bbv, 0.f));
        }
        const unsigned char* w1src = (const unsigned char*)(W1 + (size_t)i * NHID * NHID);
        uint32_t w1dst = dynb + 65536;
        #pragma unroll
        for (int c = 0; c < 4; ++c)
            CP16(w1dst + tid * 16 + c * 4096, w1src + tid * 16 + c * 4096);
        CP_COMMIT();
        CP_WAIT0();
    }
    __syncthreads();

    // ---------- layers 1+2: 2 threads per token, split output-half ----------
    {
        const float* hs  = (const float*)dyn;
        const float* W1s = (const float*)(dyn + 65536);
        int r = tid >> 1, half = tid & 1;
        float h[NHID];
        {
            float4* hv = (float4*)h;
            const float4* src = (const float4*)(hs + r * 68);
            #pragma unroll
            for (int q = 0; q < 16; ++q) hv[q] = src[q];
        }
        ull acc2[16];
        #pragma unroll
        for (int p = 0; p < 16; ++p) acc2[p] = 0ULL;
        #pragma unroll 8
        for (int k = 0; k < NHID; ++k) {
            ull hdup = pack2(h[k]);
            const ulonglong2* wr = (const ulonglong2*)(W1s + k * NHID + half * 32);
            #pragma unroll
            for (int q = 0; q < 8; ++q) {
                ulonglong2 wv = wr[q];
                acc2[2 * q]     = ffma2(hdup, wv.x, acc2[2 * q]);
                acc2[2 * q + 1] = ffma2(hdup, wv.y, acc2[2 * q + 1]);
            }
        }
        float o0 = half ? 0.f : b2_s[0];
        float o1 = half ? 0.f : b2_s[1];
        #pragma unroll
        for (int p = 0; p < 16; ++p) {
            float2 v = unpack2(acc2[p]);
            int g0 = half * 32 + 2 * p;
            float v0 = fmaxf(v.x + b1_s[g0], 0.f);
            float v1 = fmaxf(v.y + b1_s[g0 + 1], 0.f);
            o0 = fmaf(v0, W2_s[g0 * 2],     o0);
            o1 = fmaf(v0, W2_s[g0 * 2 + 1], o1);
            o0 = fmaf(v1, W2_s[g0 * 2 + 2], o0);
            o1 = fmaf(v1, W2_s[g0 * 2 + 3], o1);
        }
        po_s[tid] = make_float2(o0, o1);
    }
    __syncthreads();
    if (tid < TILE_M) {
        float2 pa = po_s[2 * tid], pb = po_s[2 * tid + 1];
        int token = tile0 + tid;
        int bb = token & (NB - 1);
        int nn = token >> 4;
        ((float2*)out)[(size_t)(bb * ND + i) * NN + nn] = make_float2(pa.x + pb.x, pa.y + pb.y);
    }
}

extern "C" void kernel_launch(void* const* d_in, const int* in_sizes, int n_in,
                              void* d_out, int out_size)
{
    const float* x  = (const float*)d_in[0];
    const float* mp = (const float*)d_in[1];
    const float* u  = (const float*)d_in[2];
    const float* W0 = (const float*)d_in[3];
    const float* b0 = (const float*)d_in[4];
    const float* W1 = (const float*)d_in[5];
    const float* b1 = (const float*)d_in[6];
    const float* W2 = (const float*)d_in[7];
    const float* b2 = (const float*)d_in[8];
    float* out = (float*)d_out;

    static int smem_set = 0;
    if (!smem_set) {
        cudaFuncSetAttribute(tsdcd_kernel, cudaFuncAttributeMaxDynamicSharedMemorySize, DYN_BYTES);
        smem_set = 1;
    }
    prep_w0<<<60, 256>>>(W0);
    dim3 grid(NTILE, ND);
    tsdcd_kernel<<<grid, TPB, DYN_BYTES>>>(x, mp, u, b0, W1, b1, W2, b2, out);
}

// round 6
// speedup vs baseline: 2.2877x; 1.2325x over previous
#include <cuda_runtime.h>
#include <cstdint>

#define NB     16
#define NTAU   10
#define ND     6
#define NN     512
#define NW     9
#define NHID   64
#define KC     54
#define TILE_M 128
#define TPB    256
#define NTILE  64
#define DYN_BYTES (98304 + 128)

typedef unsigned long long ull;

// W0 pre-converted: [i*10+t] tiles of 16KB (8KB hi + 8KB lo plane), swizzled [n][kk] bf16
__device__ __align__(1024) unsigned char g_w0bf[60 * 16384];
// A scratch: per (tile, i*10+t): 32KB (16KB hi plane + 16KB lo plane), swizzled [row][kk] bf16
__device__ __align__(1024) unsigned char g_a[(size_t)NTILE * 60 * 32768];

__device__ __forceinline__ uint32_t smem_u32(const void* p) {
    uint32_t a;
    asm("{ .reg .u64 t; cvta.to.shared.u64 t, %1; cvt.u32.u64 %0, t; }" : "=r"(a) : "l"(p));
    return a;
}
__device__ __forceinline__ ull ffma2(ull a, ull b, ull c) {
    ull d; asm("fma.rn.f32x2 %0, %1, %2, %3;" : "=l"(d) : "l"(a), "l"(b), "l"(c)); return d;
}
__device__ __forceinline__ ull pack2(float x) {
    ull d; asm("mov.b64 %0, {%1, %1};" : "=l"(d) : "f"(x)); return d;
}
__device__ __forceinline__ float2 unpack2(ull v) {
    float2 r; asm("mov.b64 {%0, %1}, %2;" : "=f"(r.x), "=f"(r.y) : "l"(v)); return r;
}
__device__ __forceinline__ uint32_t f2bf_bits(float v) {   // RNE bf16
    uint32_t u = __float_as_uint(v);
    return (u + 0x7FFFu + ((u >> 16) & 1u)) >> 16;
}
__device__ __forceinline__ uint32_t cvt_bf16x2(float hi, float lo) {
    uint32_t r; asm("cvt.rn.bf16x2.f32 %0, %1, %2;" : "=r"(r) : "f"(hi), "f"(lo)); return r;
}
__device__ __forceinline__ void stcs32(void* p, uint32_t v) {
    asm volatile("st.global.cs.b32 [%0], %1;" :: "l"(p), "r"(v));
}
__device__ __forceinline__ float2 ldcs2(const float2* p) {
    float2 r; asm volatile("ld.global.cs.v2.f32 {%0,%1}, [%2];" : "=f"(r.x), "=f"(r.y) : "l"(p)); return r;
}
__device__ __forceinline__ void ldsm4(uint32_t a, uint32_t& r0, uint32_t& r1, uint32_t& r2, uint32_t& r3) {
    asm volatile("ldmatrix.sync.aligned.m8n8.x4.shared.b16 {%0,%1,%2,%3}, [%4];"
                 : "=r"(r0), "=r"(r1), "=r"(r2), "=r"(r3) : "r"(a));
}
__device__ __forceinline__ void mma_bf16(float* d, uint32_t a0, uint32_t a1, uint32_t a2, uint32_t a3,
                                         uint32_t b0, uint32_t b1) {
    asm volatile("mma.sync.aligned.m16n8k16.row.col.f32.bf16.bf16.f32 "
                 "{%0,%1,%2,%3}, {%4,%5,%6,%7}, {%8,%9}, {%0,%1,%2,%3};"
                 : "+f"(d[0]), "+f"(d[1]), "+f"(d[2]), "+f"(d[3])
                 : "r"(a0), "r"(a1), "r"(a2), "r"(a3), "r"(b0), "r"(b1));
}
#define CP16(dst, src) asm volatile("cp.async.cg.shared.global [%0], [%1], 16;" :: "r"(dst), "l"(src))
#define CP_COMMIT()    asm volatile("cp.async.commit_group;" ::: "memory")
#define CP_WAIT0()     asm volatile("cp.async.wait_group 0;" ::: "memory")
#define CP_WAIT1()     asm volatile("cp.async.wait_group 1;" ::: "memory")

// ------------ prep: W0 -> swizzled bf16 hi/lo tile images ------------
__global__ void prep_w0(const float* __restrict__ W0)
{
    const int blk = blockIdx.x;                 // i*10 + t
    const int i = blk / 10, t = blk % 10;
    const float* src = W0 + ((size_t)i * 540 + t * KC) * NHID;
    unsigned char* hi = g_w0bf + (size_t)blk * 16384;
    unsigned char* lo = hi + 8192;
    for (int e = threadIdx.x; e < 4096; e += 256) {
        int kk = e >> 6, n = e & 63;
        float v = (kk < KC) ? src[kk * 64 + n] : 0.f;
        uint32_t hb = f2bf_bits(v);
        float hf = __uint_as_float(hb << 16);
        uint32_t lb = f2bf_bits(v - hf);
        uint32_t off = (uint32_t)(n * 128 + kk * 2) ^ ((uint32_t)(n & 7) << 4);
        *(uint16_t*)(hi + off) = (uint16_t)hb;
        *(uint16_t*)(lo + off) = (uint16_t)lb;
    }
}

// ------------ producer: m -> swizzled bf16 hi/lo A-tile images ------------
__global__ __launch_bounds__(TPB) void produce_a(
    const float* __restrict__ x,
    const float* __restrict__ mask_param,
    const float* __restrict__ u)
{
    __shared__ float E_s[KC];
    __shared__ float x_s[1632];
    __shared__ unsigned char lut_s[KC];

    const int tid  = threadIdx.x;
    const int tile = blockIdx.x;          // 0..63
    const int itx  = blockIdx.y;          // i*10 + t
    const int i = itx / 10, t = itx % 10;
    const int tile0 = tile * TILE_M;
    const int n0 = tile0 >> 4;

    if (tid < KC) {
        E_s[tid] = __expf(-mask_param[(t * ND + i) * KC + tid]);
        lut_s[tid] = (unsigned char)((tid / NW) * 16 + tid % NW);
    }
    #pragma unroll
    for (int e6 = 0; e6 < 6; ++e6) {
        int e = tid + e6 * 256;
        int colw = e & 15;
        int j = (e >> 4) % 6;
        int bb = e / 96;
        int col = n0 + colw - 4;
        float v = 0.f;
        if ((unsigned)col < NN) v = x[((bb * NTAU + t) * ND + j) * NN + col];
        x_s[(j * 16 + colw) * 17 + bb] = v;
    }
    float2 ur[14];
    #pragma unroll
    for (int it = 0; it < 14; ++it) {
        int p = tid + it * 256;
        if (p < 3456) {
            int r = (p * 4855) >> 17;         // p/27
            int q = p - r * 27;
            ur[it] = ldcs2((const float2*)(u + (size_t)(tile0 + r) * 3240 + (t * ND + i) * KC + 2 * q));
        }
    }
    __syncthreads();

    unsigned char* ahp = g_a + ((size_t)tile * 60 + itx) * 32768;
    #pragma unroll
    for (int it = 0; it < 14; ++it) {
        int p = tid + it * 256;
        if (p < 3456) {
            int r = (p * 4855) >> 17;
            int q = p - r * 27;
            int kk = 2 * q;
            float2 uv = ur[it];
            float2 ev = *(const float2*)&E_s[kk];
            int nl = r >> 4, bb = r & 15;
            float x0 = x_s[(lut_s[kk] + nl) * 17 + bb];
            float x1 = x_s[(lut_s[kk + 1] + nl) * 17 + bb];
            float m0 = x0 * __fdividef(uv.x, fmaf(ev.x, 1.f - uv.x, uv.x));
            float m1 = x1 * __fdividef(uv.y, fmaf(ev.y, 1.f - uv.y, uv.y));
            uint32_t h2 = cvt_bf16x2(m1, m0);           // lo16 = m0
            float hf0 = __uint_as_float(h2 << 16);
            float hf1 = __uint_as_float(h2 & 0xFFFF0000u);
            uint32_t l2 = cvt_bf16x2(m1 - hf1, m0 - hf0);
            uint32_t off = (uint32_t)(r * 128 + 4 * q) ^ ((uint32_t)(r & 7) << 4);
            stcs32(ahp + off,         h2);
            stcs32(ahp + 16384 + off, l2);
        }
    }
}

// ------------ consumer: GEMM (tensor cores) + layers 1/2 ------------
__global__ __launch_bounds__(TPB, 2)
void gemm_mlp(const float* __restrict__ b0,
              const float* __restrict__ W1,
              const float* __restrict__ b1,
              const float* __restrict__ W2,
              const float* __restrict__ b2,
              float* __restrict__ out)
{
    extern __shared__ unsigned char dyn_raw[];
    __shared__ float b0_s[NHID], b1_s[NHID], W2_s[128], b2_s[2];
    __shared__ float2 po_s[TPB];

    const uint32_t raw_u = smem_u32(dyn_raw);
    const uint32_t dynb  = (raw_u + 127u) & ~127u;
    unsigned char* dyn = dyn_raw + (dynb - raw_u);

    const int tid  = threadIdx.x;
    const int w    = tid >> 5;
    const int lane = tid & 31;
    const int i    = blockIdx.y;
    const int tile = blockIdx.x;
    const int tile0 = tile * TILE_M;

    if (tid < NHID) { b0_s[tid] = b0[i * NHID + tid]; b1_s[tid] = b1[i * NHID + tid]; }
    if (tid < 128) W2_s[tid] = W2[i * 128 + tid];
    if (tid < 2)   b2_s[tid] = b2[i * 2 + tid];

    float d[8][4];
    #pragma unroll
    for (int q = 0; q < 8; ++q)
        #pragma unroll
        for (int c = 0; c < 4; ++c) d[q][c] = 0.f;

    // per-lane ldmatrix geometry
    const int rowA = (w << 4) + (lane & 15);
    const uint32_t aoff = (uint32_t)rowA * 128;
    const uint32_t axr  = (uint32_t)(rowA & 7) << 4;
    const int nB_ = lane & 15;
    const uint32_t bxr  = (uint32_t)(nB_ & 7) << 4;
    const uint32_t colsel = (uint32_t)(lane >> 4) << 4;

    auto prefetch = [&](int t) {
        const unsigned char* asrc = g_a + ((size_t)tile * 60 + i * 10 + t) * 32768;
        uint32_t adst = dynb + (uint32_t)(t & 1) * 32768;
        #pragma unroll
        for (int c = 0; c < 8; ++c)
            CP16(adst + tid * 16 + c * 4096, asrc + tid * 16 + c * 4096);
        const unsigned char* bsrc = g_w0bf + (size_t)(i * 10 + t) * 16384;
        uint32_t bdst = dynb + 65536 + (uint32_t)(t & 1) * 16384;
        #pragma unroll
        for (int c = 0; c < 4; ++c)
            CP16(bdst + tid * 16 + c * 4096, bsrc + tid * 16 + c * 4096);
        CP_COMMIT();
    };
    auto consume = [&](int s) {
        uint32_t Abase = dynb + (uint32_t)s * 32768;
        uint32_t Bbase = dynb + 65536 + (uint32_t)s * 16384;
        #pragma unroll
        for (int k = 0; k < 4; ++k) {
            uint32_t colb = (uint32_t)k * 32 + colsel;
            uint32_t aa = Abase + aoff + (colb ^ axr);
            uint32_t ah0, ah1, ah2, ah3, al0, al1, al2, al3;
            ldsm4(aa,         ah0, ah1, ah2, ah3);
            ldsm4(aa + 16384, al0, al1, al2, al3);
            #pragma unroll
            for (int g = 0; g < 4; ++g) {
                uint32_t ba = Bbase + ((uint32_t)g << 11) + (uint32_t)nB_ * 128 + (colb ^ bxr);
                uint32_t bh0, bh1, bh2, bh3, bl0, bl1, bl2, bl3;
                ldsm4(ba,        bh0, bh1, bh2, bh3);
                ldsm4(ba + 8192, bl0, bl1, bl2, bl3);
                mma_bf16(d[2 * g],     ah0, ah1, ah2, ah3, bh0, bh2);
                mma_bf16(d[2 * g],     al0, al1, al2, al3, bh0, bh2);
                mma_bf16(d[2 * g],     ah0, ah1, ah2, ah3, bl0, bl2);
                mma_bf16(d[2 * g + 1], ah0, ah1, ah2, ah3, bh1, bh3);
                mma_bf16(d[2 * g + 1], al0, al1, al2, al3, bh1, bh3);
                mma_bf16(d[2 * g + 1], ah0, ah1, ah2, ah3, bl1, bl3);
            }
        }
    };

    prefetch(0);
    prefetch(1);
    for (int t = 0; t < NTAU; ++t) {
        if (t < NTAU - 1) CP_WAIT1(); else CP_WAIT0();
        __syncthreads();
        consume(t & 1);
        __syncthreads();
        if (t < NTAU - 2) prefetch(t + 2);
    }

    // ---------- epilogue: bias+relu -> h_s (stride 68), stage W1 ----------
    {
        float* hs = (float*)dyn;
        int rb = (w << 4) + (lane >> 2);
        int cb = (lane & 3) * 2;
        #pragma unroll
        for (int nt = 0; nt < 8; ++nt) {
            int c = nt * 8 + cb;
            float ba = b0_s[c], bbv = b0_s[c + 1];
            *(float2*)&hs[rb * 68 + c]       = make_float2(fmaxf(d[nt][0] + ba, 0.f), fmaxf(d[nt][1] + bbv, 0.f));
            *(float2*)&hs[(rb + 8) * 68 + c] = make_float2(fmaxf(d[nt][2] + ba, 0.f), fmaxf(d[nt][3] + bbv, 0.f));
        }
        const unsigned char* w1src = (const unsigned char*)(W1 + (size_t)i * NHID * NHID);
        uint32_t w1dst = dynb + 65536;
        #pragma unroll
        for (int c = 0; c < 4; ++c)
            CP16(w1dst + tid * 16 + c * 4096, w1src + tid * 16 + c * 4096);
        CP_COMMIT();
        CP_WAIT0();
    }
    __syncthreads();

    // ---------- layers 1+2: 2 threads per token, split output-half ----------
    {
        const float* hs  = (const float*)dyn;
        const float* W1s = (const float*)(dyn + 65536);
        int r = tid >> 1, half = tid & 1;
        float h[NHID];
        {
            float4* hv = (float4*)h;
            const float4* src = (const float4*)(hs + r * 68);
            #pragma unroll
            for (int q = 0; q < 16; ++q) hv[q] = src[q];
        }
        ull acc2[16];
        #pragma unroll
        for (int p = 0; p < 16; ++p) acc2[p] = 0ULL;
        #pragma unroll 8
        for (int k = 0; k < NHID; ++k) {
            ull hdup = pack2(h[k]);
            const ulonglong2* wr = (const ulonglong2*)(W1s + k * NHID + half * 32);
            #pragma unroll
            for (int q = 0; q < 8; ++q) {
                ulonglong2 wv = wr[q];
                acc2[2 * q]     = ffma2(hdup, wv.x, acc2[2 * q]);
                acc2[2 * q + 1] = ffma2(hdup, wv.y, acc2[2 * q + 1]);
            }
        }
        float o0 = half ? 0.f : b2_s[0];
        float o1 = half ? 0.f : b2_s[1];
        #pragma unroll
        for (int p = 0; p < 16; ++p) {
            float2 v = unpack2(acc2[p]);
            int g0 = half * 32 + 2 * p;
            float v0 = fmaxf(v.x + b1_s[g0], 0.f);
            float v1 = fmaxf(v.y + b1_s[g0 + 1], 0.f);
            o0 = fmaf(v0, W2_s[g0 * 2],     o0);
            o1 = fmaf(v0, W2_s[g0 * 2 + 1], o1);
            o0 = fmaf(v1, W2_s[g0 * 2 + 2], o0);
            o1 = fmaf(v1, W2_s[g0 * 2 + 3], o1);
        }
        po_s[tid] = make_float2(o0, o1);
    }
    __syncthreads();
    if (tid < TILE_M) {
        float2 pa = po_s[2 * tid], pb = po_s[2 * tid + 1];
        int token = tile0 + tid;
        int bb = token & (NB - 1);
        int nn = token >> 4;
        ((float2*)out)[(size_t)(bb * ND + i) * NN + nn] = make_float2(pa.x + pb.x, pa.y + pb.y);
    }
}

extern "C" void kernel_launch(void* const* d_in, const int* in_sizes, int n_in,
                              void* d_out, int out_size)
{
    const float* x  = (const float*)d_in[0];
    const float* mp = (const float*)d_in[1];
    const float* u  = (const float*)d_in[2];
    const float* W0 = (const float*)d_in[3];
    const float* b0 = (const float*)d_in[4];
    const float* W1 = (const float*)d_in[5];
    const float* b1 = (const float*)d_in[6];
    const float* W2 = (const float*)d_in[7];
    const float* b2 = (const float*)d_in[8];
    float* out = (float*)d_out;

    static int smem_set = 0;
    if (!smem_set) {
        cudaFuncSetAttribute(gemm_mlp, cudaFuncAttributeMaxDynamicSharedMemorySize, DYN_BYTES);
        smem_set = 1;
    }
    prep_w0<<<60, 256>>>(W0);
    produce_a<<<dim3(NTILE, 60), TPB>>>(x, mp, u);
    gemm_mlp<<<dim3(NTILE, ND), TPB, DYN_BYTES>>>(b0, W1, b1, W2, b2, out);
}